// round 8
// baseline (speedup 1.0000x reference)
#include <cuda_runtime.h>

#define IN_SIZE 448
#define OUT_SIZE 224
#define BATCH 64
#define NTHREADS 224
#define RPB 8                 // rows per unit
#define UNITS_PER_BLK 2       // units are 112 rows apart, same batch
#define GRID_BLKS 896         // 14 rowgroups x 64 batches; unit i and i+896 share batch

// fast sigmoid(10z): MUFU-based; saturates exactly to 0/1 for |z| >~ 4.
__device__ __forceinline__ float sig10f(float z) {
    return 1.0f / (1.0f + __expf(-10.0f * z));
}

__global__ void __launch_bounds__(NTHREADS) racnn_fused(
    const float* __restrict__ images,
    const float* __restrict__ locs,
    float* __restrict__ out)
{
    __shared__ float4 s_rowe[RPB * UNITS_PER_BLK];  // 16 row entries

    const int b   = blockIdx.x & 63;        // batch
    const int rg0 = blockIdx.x >> 6;        // rowgroup 0..13; units: rg0, rg0+14
    const int jc  = threadIdx.x;

    // ---- per-batch crop params (broadcast) ----
    float tx = locs[b * 3 + 0];
    float ty = locs[b * 3 + 1];
    float tl = locs[b * 3 + 2];

    tl = fmaxf(tl, 448.0f / 3.0f);
    tx = fminf(fmaxf(tx, tl), (float)IN_SIZE - tl);
    ty = fminf(fmaxf(ty, tl), (float)IN_SIZE - tl);

    const float w_off = fmaxf(floorf(tx - tl), 0.0f);
    const float h_off = fmaxf(floorf(ty - tl), 0.0f);
    const float w_end = fminf(floorf(tx + tl), (float)IN_SIZE);
    const float h_end = fminf(floorf(ty + tl), (float)IN_SIZE);

    // ---- 16 row entries: threads 0..15 (exact sigmoids, cheap) ----
    if (jc < RPB * UNITS_PER_BLK) {
        const int unit = jc >> 3;           // 0 or 1
        const int r    = jc & 7;
        const int jr   = rg0 * RPB + unit * 112 + r;
        const float jf = (float)jr;
        const float src_r = w_off + (jf * (w_end - w_off - 1.0f)) / (float)(OUT_SIZE - 1);
        float r0 = fminf(fmaxf(floorf(src_r), 0.0f), (float)(IN_SIZE - 1));
        const float wr = src_r - r0;
        const int r0i = (int)r0;
        const int r1i = min(r0i + 1, IN_SIZE - 1);
        const float mrow0 = sig10f((float)r0i - w_off) - sig10f((float)r0i - w_end);
        const float mrow1 = sig10f((float)r1i - w_off) - sig10f((float)r1i - w_end);
        float4 e;
        e.x = __int_as_float(r0i * IN_SIZE);
        e.y = __int_as_float(r1i * IN_SIZE);
        e.z = (1.0f - wr) * mrow0;
        e.w = wr * mrow1;
        s_rowe[jc] = e;
    }

    // ---- col entry: per thread, saturation fast path for middle warps ----
    // Min col stride = 297/223 = 1.332; for 32<=jc<192 the mask sigmoid args
    // have |z| >= 41 -> sig10 saturates exactly to 0/1 in fp32.
    const float jf = (float)jc;
    const float src_c = h_off + (jf * (h_end - h_off - 1.0f)) / (float)(OUT_SIZE - 1);
    float c0 = fminf(fmaxf(floorf(src_c), 0.0f), (float)(IN_SIZE - 1));
    const float wc = src_c - c0;
    const int c0i = (int)c0;
    const int c1i = min(c0i + 1, IN_SIZE - 1);

    float mcol0 = 1.0f, mcol1 = 1.0f;
    if (jc < 32 || jc >= 192) {   // warp-uniform branch (warps 0 and 6)
        mcol0 = sig10f((float)c0i - h_off) - sig10f((float)c0i - h_end);
        mcol1 = sig10f((float)c1i - h_off) - sig10f((float)c1i - h_end);
    }
    const float b0 = (1.0f - wc) * mcol0;
    const float b1 = wc * mcol1;

    __syncthreads();

    const int img_base = b * 3 * IN_SIZE * IN_SIZE;

#pragma unroll
    for (int unit = 0; unit < UNITS_PER_BLK; unit++) {
        const int jr0 = rg0 * RPB + unit * 112;
        const int out_base = b * 3 * OUT_SIZE * OUT_SIZE + jr0 * OUT_SIZE + jc;

#pragma unroll
        for (int r = 0; r < RPB; r++) {
            const float4 re = s_rowe[unit * RPB + r];
            const int   p0 = img_base + __float_as_int(re.x);
            const int   p1 = img_base + __float_as_int(re.y);
            const float a0 = re.z;
            const float a1 = re.w;

            float x00[3], x01[3], x10[3], x11[3];
#pragma unroll
            for (int ch = 0; ch < 3; ch++) {
                const int cofs = ch * (IN_SIZE * IN_SIZE);
                x00[ch] = __ldg(images + p0 + cofs + c0i);
                x01[ch] = __ldg(images + p0 + cofs + c1i);
                x10[ch] = __ldg(images + p1 + cofs + c0i);
                x11[ch] = __ldg(images + p1 + cofs + c1i);
            }
#pragma unroll
            for (int ch = 0; ch < 3; ch++) {
                const float top = fmaf(b1, x01[ch], b0 * x00[ch]);
                const float bot = fmaf(b1, x11[ch], b0 * x10[ch]);
                const float v = fmaf(a1, bot, a0 * top);
                __stcs(out + out_base + ch * (OUT_SIZE * OUT_SIZE) + r * OUT_SIZE, v);
            }
        }
    }
}

extern "C" void kernel_launch(void* const* d_in, const int* in_sizes, int n_in,
                              void* d_out, int out_size) {
    const float* images = (const float*)d_in[0];
    const float* locs   = (const float*)d_in[1];
    float* out = (float*)d_out;

    racnn_fused<<<GRID_BLKS, NTHREADS>>>(images, locs, out);
}

// round 9
// speedup vs baseline: 1.0703x; 1.0703x over previous
#include <cuda_runtime.h>

#define IN_SIZE 448
#define OUT_SIZE 224
#define BATCH 64
#define NTHREADS 224
#define ROWS_PER_BLK 8

// fast sigmoid(10z): MUFU-based; saturates exactly to 0/1 for |10z| large.
__device__ __forceinline__ float sig10f(float z) {
    return 1.0f / (1.0f + __expf(-10.0f * z));
}

// ---------------------------------------------------------------------------
// Fused kernel. grid=(28, 64), block=224. Each block: 8 output rows.
// R7 structure (best measured) + warp-uniform saturation fast path for the
// column-mask sigmoids (exact in fp32 for threads 32..191).
// ---------------------------------------------------------------------------
__global__ void __launch_bounds__(NTHREADS) racnn_fused(
    const float* __restrict__ images,
    const float* __restrict__ locs,
    float* __restrict__ out)
{
    __shared__ float4 s_rowe[ROWS_PER_BLK];  // {r0off(int bits), r1off(int bits), a0, a1}

    const int jr0 = blockIdx.x * ROWS_PER_BLK;
    const int b   = blockIdx.y;
    const int jc  = threadIdx.x;

    // ---- per-batch crop params (broadcast) ----
    float tx = locs[b * 3 + 0];
    float ty = locs[b * 3 + 1];
    float tl = locs[b * 3 + 2];

    tl = fmaxf(tl, 448.0f / 3.0f);
    tx = fminf(fmaxf(tx, tl), (float)IN_SIZE - tl);
    ty = fminf(fmaxf(ty, tl), (float)IN_SIZE - tl);

    const float w_off = fmaxf(floorf(tx - tl), 0.0f);
    const float h_off = fmaxf(floorf(ty - tl), 0.0f);
    const float w_end = fminf(floorf(tx + tl), (float)IN_SIZE);
    const float h_end = fminf(floorf(ty + tl), (float)IN_SIZE);

    // ---- row entries: threads 0..7 ----
    if (jc < ROWS_PER_BLK) {
        const float jf = (float)(jr0 + jc);
        const float src_r = w_off + (jf * (w_end - w_off - 1.0f)) / (float)(OUT_SIZE - 1);
        float r0 = fminf(fmaxf(floorf(src_r), 0.0f), (float)(IN_SIZE - 1));
        const float wr = src_r - r0;
        const int r0i = (int)r0;
        const int r1i = min(r0i + 1, IN_SIZE - 1);
        const float mrow0 = sig10f((float)r0i - w_off) - sig10f((float)r0i - w_end);
        const float mrow1 = sig10f((float)r1i - w_off) - sig10f((float)r1i - w_end);
        float4 e;
        e.x = __int_as_float(r0i * IN_SIZE);
        e.y = __int_as_float(r1i * IN_SIZE);
        e.z = (1.0f - wr) * mrow0;
        e.w = wr * mrow1;
        s_rowe[jc] = e;
    }

    // ---- col entry: per thread; saturation fast path for middle warps ----
    // Col stride = (h_end-h_off-1)/223 >= 297/223 = 1.332. For 32<=jc<192 the
    // sigmoid args are >= ~41 in magnitude with the right signs -> mcol == 1
    // exactly in fp32. Branch is warp-uniform (warps 1..5 skip MUFUs).
    const float jf = (float)jc;
    const float src_c = h_off + (jf * (h_end - h_off - 1.0f)) / (float)(OUT_SIZE - 1);
    float c0 = fminf(fmaxf(floorf(src_c), 0.0f), (float)(IN_SIZE - 1));
    const float wc = src_c - c0;
    const int c0i = (int)c0;
    const int c1i = min(c0i + 1, IN_SIZE - 1);

    float mcol0 = 1.0f, mcol1 = 1.0f;
    if (jc < 32 || jc >= 192) {
        mcol0 = sig10f((float)c0i - h_off) - sig10f((float)c0i - h_end);
        mcol1 = sig10f((float)c1i - h_off) - sig10f((float)c1i - h_end);
    }
    const float b0 = (1.0f - wc) * mcol0;
    const float b1 = wc * mcol1;

    __syncthreads();

    const int img_base = b * 3 * IN_SIZE * IN_SIZE;
    const int out_base = b * 3 * OUT_SIZE * OUT_SIZE + jr0 * OUT_SIZE + jc;

    // ---- gather: one row per iteration, 12-load batches ----
#pragma unroll
    for (int r = 0; r < ROWS_PER_BLK; r++) {
        const float4 re = s_rowe[r];
        const int   p0 = img_base + __float_as_int(re.x);
        const int   p1 = img_base + __float_as_int(re.y);
        const float a0 = re.z;
        const float a1 = re.w;

        float x00[3], x01[3], x10[3], x11[3];
#pragma unroll
        for (int ch = 0; ch < 3; ch++) {
            const int cofs = ch * (IN_SIZE * IN_SIZE);
            x00[ch] = __ldg(images + p0 + cofs + c0i);
            x01[ch] = __ldg(images + p0 + cofs + c1i);
            x10[ch] = __ldg(images + p1 + cofs + c0i);
            x11[ch] = __ldg(images + p1 + cofs + c1i);
        }
#pragma unroll
        for (int ch = 0; ch < 3; ch++) {
            const float top = fmaf(b1, x01[ch], b0 * x00[ch]);
            const float bot = fmaf(b1, x11[ch], b0 * x10[ch]);
            const float v = fmaf(a1, bot, a0 * top);
            __stcs(out + out_base + ch * (OUT_SIZE * OUT_SIZE) + r * OUT_SIZE, v);
        }
    }
}

extern "C" void kernel_launch(void* const* d_in, const int* in_sizes, int n_in,
                              void* d_out, int out_size) {
    const float* images = (const float*)d_in[0];
    const float* locs   = (const float*)d_in[1];
    float* out = (float*)d_out;

    dim3 grid(OUT_SIZE / ROWS_PER_BLK, BATCH);
    racnn_fused<<<grid, NTHREADS>>>(images, locs, out);
}